// round 16
// baseline (speedup 1.0000x reference)
#include <cuda_runtime.h>
#include <cstdint>

#define BB 4
#define NN 4096
#define KNN 9
#define KS 4
#define CHUNK (NN/KS)
#define BN_TOT (BB*NN)
#define NEG_INF (-3.402823466e38f)

// ---------------- device scratch ----------------
__device__ int   d_idx[BN_TOT*KNN];
__device__ float d_candD[BN_TOT*KS*KNN];
__device__ int   d_candI[BN_TOT*KS*KNN];
__device__ float d_G1[BN_TOT*128];
__device__ float d_G2D[BN_TOT*384];     // conv2 [U|Z] cols 0..255, dec cols 256..303 (pad to 384)
__device__ float d_G3[BN_TOT*512];
__device__ float d_G4[BN_TOT*512];
__device__ float d_fused[BN_TOT*256];
__device__ float d_part1[512*256];
__device__ float d_part2[512*256];
__device__ __align__(16) float d_scaleA[5][256];
__device__ __align__(16) float d_shiftA[5][256];
__device__ __align__(16) uint32_t d_Ah[BN_TOT*160];
__device__ __align__(16) uint32_t d_Al[BN_TOT*160];
__device__ __align__(16) uint32_t d_WhAll[151552];
__device__ __align__(16) uint32_t d_WlAll[151552];
__device__ float d_pool[4*16*512];
__device__ float d_h[4*512];
__device__ float d_y1[4*256];
__device__ float d_h2[4*256];

// W segment offsets (u32): combined conv2+dec, conv3, conv4, fus
#define WOFF_C2D  0              // 384 rows x 32
#define WOFF_DEC  8192           //   dec sub-block at row 256
#define WOFF_C3   12288          // 512 x 64
#define WOFF_C4   45056          // 512 x 128
#define WOFF_FUS  110592         // 256 x 160

// ---------------- helpers ----------------
__device__ __forceinline__ float sq3(float a, float b, float c) {
    return a*a + b*b + c*c;
}
__device__ __forceinline__ uint32_t pack_bf16(float a0, float a1) {
    uint32_t r; asm("cvt.rn.bf16x2.f32 %0, %1, %2;" : "=r"(r) : "f"(a1), "f"(a0));
    return r;
}
__device__ __forceinline__ void split_bf16(float v0, float v1, uint32_t& h, uint32_t& l) {
    h = pack_bf16(v0, v1);
    l = pack_bf16(v0 - __uint_as_float(h << 16),
                  v1 - __uint_as_float(h & 0xffff0000u));
}
__device__ __forceinline__ void mma16(float* d, uint32_t a0, uint32_t a1, uint32_t a2, uint32_t a3,
                                      uint32_t b0, uint32_t b1) {
    asm volatile(
        "mma.sync.aligned.m16n8k16.row.col.f32.bf16.bf16.f32 "
        "{%0,%1,%2,%3},{%4,%5,%6,%7},{%8,%9},{%0,%1,%2,%3};"
        : "+f"(d[0]), "+f"(d[1]), "+f"(d[2]), "+f"(d[3])
        : "r"(a0), "r"(a1), "r"(a2), "r"(a3), "r"(b0), "r"(b1));
}
__device__ __forceinline__ uint32_t smem_u32(const void* p) {
    uint32_t a;
    asm("{ .reg .u64 t; cvta.to.shared.u64 t, %1; cvt.u32.u64 %0, t; }" : "=r"(a) : "l"(p));
    return a;
}
#define LDSM4(r0,r1,r2,r3,addr) \
    asm volatile("ldmatrix.sync.aligned.m8n8.x4.shared.b16 {%0,%1,%2,%3}, [%4];" \
        : "=r"(r0),"=r"(r1),"=r"(r2),"=r"(r3) : "r"(addr))
#define CP_ASYNC16(s, g) \
    asm volatile("cp.async.cg.shared.global [%0], [%1], 16;" :: "r"(s), "l"(g))
#define CP_COMMIT()  asm volatile("cp.async.commit_group;" ::: "memory")
#define CP_WAIT1()   asm volatile("cp.async.wait_group 1;" ::: "memory")

// ---------------- knn (reads x directly; x layout (b,3,N)) ----------------
__global__ void knn_part_kernel(const float* __restrict__ x,
                                float* __restrict__ candD, int* __restrict__ candI) {
    __shared__ float sx[CHUNK], sy[CHUNK], sz[CHUNK], s2[CHUNK];
    int b  = blockIdx.x;
    int n  = blockIdx.y * blockDim.x + threadIdx.x;
    int cs = blockIdx.z;
    int m0 = cs * CHUNK;
    const float* xb0 = x + (size_t)(b*3+0)*NN;
    const float* xb1 = x + (size_t)(b*3+1)*NN;
    const float* xb2 = x + (size_t)(b*3+2)*NN;
    for (int t = threadIdx.x; t < CHUNK; t += blockDim.x) {
        int m = m0 + t;
        float a = xb0[m], bb = xb1[m], c = xb2[m];
        sx[t] = a; sy[t] = bb; sz[t] = c;
        s2[t] = sq3(a, bb, c);
    }
    __syncthreads();
    float px = xb0[n], py = xb1[n], pz = xb2[n];
    float p2 = sq3(px, py, pz);
    float bd[KNN]; int bi[KNN];
#pragma unroll
    for (int j = 0; j < KNN; ++j) { bd[j] = 1e30f; bi[j] = 0; }
#pragma unroll 4
    for (int mm = 0; mm < CHUNK; ++mm) {
        float dot = px*sx[mm] + py*sy[mm] + pz*sz[mm];
        float d = p2 + s2[mm] - 2.0f*dot;
        int m = m0 + mm;
        if (m == n) d = 1e30f;
        if (d < bd[KNN-1]) {
            float vd = d; int vi = m;
#pragma unroll
            for (int j = 0; j < KNN; ++j) {
                if (vd < bd[j]) {
                    float td = bd[j]; bd[j] = vd; vd = td;
                    int   ti = bi[j]; bi[j] = vi; vi = ti;
                }
            }
        }
    }
    size_t base = ((size_t)(b*NN + n)*KS + cs)*KNN;
#pragma unroll
    for (int j = 0; j < KNN; ++j) {
        candD[base + j] = bd[j];
        candI[base + j] = bi[j];
    }
}

__global__ void knn_merge_kernel(const float* __restrict__ candD, const int* __restrict__ candI,
                                 int* __restrict__ idxOut) {
    int t = blockIdx.x * blockDim.x + threadIdx.x;
    if (t >= BN_TOT) return;
    int b = t / NN;
    float bd[KNN]; int bi[KNN];
#pragma unroll
    for (int j = 0; j < KNN; ++j) { bd[j] = 1e30f; bi[j] = 0; }
    size_t base = (size_t)t*KS*KNN;
    for (int c = 0; c < KS*KNN; ++c) {
        float d = candD[base + c];
        int   m = candI[base + c];
        if (d < bd[KNN-1]) {
            float vd = d; int vi = m;
#pragma unroll
            for (int j = 0; j < KNN; ++j) {
                if (vd < bd[j]) {
                    float td = bd[j]; bd[j] = vd; vd = td;
                    int   ti = bi[j]; bi[j] = vi; vi = ti;
                }
            }
        }
    }
#pragma unroll
    for (int j = 0; j < KNN; ++j)
        idxOut[t*KNN + j] = b*NN + bi[j];
}

// ---------------- conv1 (Kc=3, reads x directly) ----------------
__global__ void conv1_kernel(const float* __restrict__ x, const float* __restrict__ w1,
                             float* __restrict__ G) {
    __shared__ float cw0[128], cw1[128], cw2[128];
    int tid = threadIdx.x;
    if (tid < 128) {
        if (tid < 64) {
            cw0[tid] = w1[tid*6+0] - w1[tid*6+3];
            cw1[tid] = w1[tid*6+1] - w1[tid*6+4];
            cw2[tid] = w1[tid*6+2] - w1[tid*6+5];
        } else {
            int q = tid - 64;
            cw0[tid] = w1[q*6+3]; cw1[tid] = w1[q*6+4]; cw2[tid] = w1[q*6+5];
        }
    }
    __syncthreads();
    int t4 = blockIdx.x * blockDim.x + tid;
    if (t4 >= BN_TOT*128/4) return;
    int t = t4 * 4;
    int p = t >> 7, o = t & 127;
    int b = p >> 12, n = p & (NN - 1);
    float x0 = x[(size_t)(b*3+0)*NN + n];
    float x1 = x[(size_t)(b*3+1)*NN + n];
    float x2 = x[(size_t)(b*3+2)*NN + n];
    float4 r;
    r.x = cw0[o+0]*x0 + cw1[o+0]*x1 + cw2[o+0]*x2;
    r.y = cw0[o+1]*x0 + cw1[o+1]*x1 + cw2[o+1]*x2;
    r.z = cw0[o+2]*x0 + cw1[o+2]*x1 + cw2[o+2]*x2;
    r.w = cw0[o+3]*x0 + cw1[o+3]*x1 + cw2[o+3]*x2;
    *(float4*)&G[t] = r;
}

// ---------------- all weight packs in ONE launch ----------------
__device__ __forceinline__ void pack_w_seg(const float* __restrict__ W, int wmode, int O, int Nc,
                                           int Kc, int K2, int Npad,
                                           uint32_t* __restrict__ Wh, uint32_t* __restrict__ Wl) {
    int total = Npad * K2;
    for (int t = blockIdx.x * blockDim.x + threadIdx.x; t < total; t += gridDim.x * blockDim.x) {
        int n = t / K2, k2 = t % K2;
        int k = 2*k2;
        float v0 = 0.f, v1 = 0.f;
        if (k < Kc) {
            if (wmode == 1) {
                if (n < O) {
                    v0 = W[(size_t)n*2*Kc + k]     - W[(size_t)n*2*Kc + Kc + k];
                    v1 = W[(size_t)n*2*Kc + k + 1] - W[(size_t)n*2*Kc + Kc + k + 1];
                } else if (n < 2*O) {
                    v0 = W[(size_t)(n-O)*2*Kc + Kc + k];
                    v1 = W[(size_t)(n-O)*2*Kc + Kc + k + 1];
                }
            } else if (n < Nc) {
                v0 = W[(size_t)n*Kc + k];
                v1 = W[(size_t)n*Kc + k + 1];
            }
        }
        uint32_t h, l; split_bf16(v0, v1, h, l);
        Wh[t] = h; Wl[t] = l;
    }
}

__global__ void convW_all_kernel(const float* __restrict__ w2, const float* __restrict__ w3,
                                 const float* __restrict__ w4, const float* __restrict__ dec_w,
                                 const float* __restrict__ fus_w,
                                 uint32_t* __restrict__ Wh, uint32_t* __restrict__ Wl) {
    switch (blockIdx.y) {
        case 0: pack_w_seg(w2,    1, 128, 256,  64,  32, 256, Wh + WOFF_C2D, Wl + WOFF_C2D); break;
        case 1: pack_w_seg(w3,    1, 256, 512, 128,  64, 512, Wh + WOFF_C3,  Wl + WOFF_C3);  break;
        case 2: pack_w_seg(w4,    1, 256, 512, 256, 128, 512, Wh + WOFF_C4,  Wl + WOFF_C4);  break;
        case 3: pack_w_seg(dec_w, 0,   0,  48,  64,  32, 128, Wh + WOFF_DEC, Wl + WOFF_DEC); break;
        case 4: pack_w_seg(fus_w, 0,   0, 256, 304, 160, 256, Wh + WOFF_FUS, Wl + WOFF_FUS); break;
    }
}

// ---------------- preconvert A (lda-strided source) ----------------
__global__ void convA_kernel(const float* __restrict__ src, int lda, int Kc, int K2,
                             int stage, uint32_t* __restrict__ Ah, uint32_t* __restrict__ Al) {
    int t = blockIdx.x * blockDim.x + threadIdx.x;
    if (t >= BN_TOT*K2) return;
    int p = t / K2, k2 = t % K2;
    int k = 2*k2;
    float v0 = 0.f, v1 = 0.f;
    if (k < Kc) {
        v0 = src[(size_t)p*lda + k];
        v1 = src[(size_t)p*lda + k + 1];
        if (stage >= 0) {
            v0 = fmaxf(fmaf(v0, d_scaleA[stage][k],   d_shiftA[stage][k]),   0.0f);
            v1 = fmaxf(fmaf(v1, d_scaleA[stage][k+1], d_shiftA[stage][k+1]), 0.0f);
        }
    }
    uint32_t h, l; split_bf16(v0, v1, h, l);
    Ah[t] = h; Al[t] = l;
}

// ---------------- cat -> packed (Gdec inside G2D at col 256, stride 384) ----------------
__global__ void convCat_kernel(const float* __restrict__ G4, const float* __restrict__ G2D,
                               uint32_t* __restrict__ Ah, uint32_t* __restrict__ Al) {
    int t = blockIdx.x * blockDim.x + threadIdx.x;
    if (t >= BN_TOT*160) return;
    int p = t / 160, k2 = t % 160;
    int k = 2*k2;
    float v0 = 0.f, v1 = 0.f;
    if (k < 256) {
        v0 = fmaxf(fmaf(G4[(size_t)p*512 + k],   d_scaleA[3][k],   d_shiftA[3][k]),   0.0f);
        v1 = fmaxf(fmaf(G4[(size_t)p*512 + k+1], d_scaleA[3][k+1], d_shiftA[3][k+1]), 0.0f);
    } else if (k < 304) {
        int q = k - 256;
        v0 = fmaxf(fmaf(G2D[(size_t)p*384 + 256 + q],   d_scaleA[4][q],   d_shiftA[4][q]),   0.0f);
        if (q + 1 < 48)
            v1 = fmaxf(fmaf(G2D[(size_t)p*384 + 256 + q+1], d_scaleA[4][q+1], d_shiftA[4][q+1]), 0.0f);
    }
    uint32_t h, l; split_bf16(v0, v1, h, l);
    Ah[t] = h; Al[t] = l;
}

// ---------------- bf16x3 GEMM ----------------
#define GS_ROW 20
#define GS_ARR (128*GS_ROW)
#define GS_BUF (4*GS_ARR)
#define GEMM_SMEM (2*GS_BUF*4)

__global__ __launch_bounds__(256, 2)
void bf_gemm(const uint32_t* __restrict__ Ah, const uint32_t* __restrict__ Al, int sK2,
             const uint32_t* __restrict__ Wh, const uint32_t* __restrict__ Wl,
             float* __restrict__ C, int Nc, int nIter) {
    extern __shared__ uint32_t sm[];
    uint32_t sbase = smem_u32(sm);

    int tid = threadIdx.x;
    int lane = tid & 31, wid = tid >> 5;
    int wm = wid >> 2, wn = wid & 3;
    int g = lane >> 2, tig = lane & 3;
    int bm = blockIdx.x * 128;
    int bn = blockIdx.y * 128;

    float d[4][4][4];
#pragma unroll
    for (int i = 0; i < 4; ++i)
#pragma unroll
        for (int j = 0; j < 4; ++j)
#pragma unroll
            for (int q = 0; q < 4; ++q) d[i][j][q] = 0.0f;

#define ISSUE_LOADS(IT, BUFO)                                                   \
    {                                                                           \
        int k2o = (IT)*16;                                                      \
        _Pragma("unroll")                                                       \
        for (int i = 0; i < 8; ++i) {                                           \
            int c   = tid + i*256;                                              \
            int arr = c >> 9;                                                   \
            int rr  = (c & 511) >> 2;                                           \
            int col = c & 3;                                                    \
            const uint32_t* gp;                                                 \
            if (arr == 0)      gp = Ah + (size_t)(bm + rr)*sK2 + k2o + col*4;   \
            else if (arr == 1) gp = Al + (size_t)(bm + rr)*sK2 + k2o + col*4;   \
            else if (arr == 2) gp = Wh + (size_t)(bn + rr)*sK2 + k2o + col*4;   \
            else               gp = Wl + (size_t)(bn + rr)*sK2 + k2o + col*4;   \
            uint32_t sa = sbase + ((BUFO) + arr*GS_ARR + rr*GS_ROW + col*4)*4;  \
            CP_ASYNC16(sa, gp);                                                 \
        }                                                                       \
    }

    ISSUE_LOADS(0, 0)
    CP_COMMIT();

    int aRow = ((lane >> 3) & 1)*8 + (lane & 7);
    int aChk = lane >> 4;
    int bRow = ((lane >> 4) & 1)*8 + (lane & 7);
    int bChk = (lane >> 3) & 1;

    for (int it = 0; it < nIter; ++it) {
        int bufo = (it & 1) * GS_BUF;
        int nxto = ((it + 1) & 1) * GS_BUF;
        if (it + 1 < nIter) ISSUE_LOADS(it + 1, nxto)
        CP_COMMIT();
        CP_WAIT1();
        __syncthreads();

        uint32_t ahB = sbase + (bufo + 0*GS_ARR)*4;
        uint32_t alB = sbase + (bufo + 1*GS_ARR)*4;
        uint32_t bhB = sbase + (bufo + 2*GS_ARR)*4;
        uint32_t blB = sbase + (bufo + 3*GS_ARR)*4;

#pragma unroll
        for (int ks = 0; ks < 2; ++ks) {
            uint32_t bh[4][2], bl[4][2];
#pragma unroll
            for (int p = 0; p < 2; ++p) {
                uint32_t off = ((wn*32 + p*16 + bRow)*GS_ROW + (ks*2 + bChk)*4)*4;
                LDSM4(bh[2*p][0], bh[2*p][1], bh[2*p+1][0], bh[2*p+1][1], bhB + off);
                LDSM4(bl[2*p][0], bl[2*p][1], bl[2*p+1][0], bl[2*p+1][1], blB + off);
            }
#pragma unroll
            for (int mt = 0; mt < 4; ++mt) {
                uint32_t a0, a1, a2, a3, l0, l1, l2, l3;
                uint32_t off = ((wm*64 + mt*16 + aRow)*GS_ROW + (ks*2 + aChk)*4)*4;
                LDSM4(a0, a1, a2, a3, ahB + off);
                LDSM4(l0, l1, l2, l3, alB + off);
                // term-major sweep: consecutive MMAs hit different accumulators
#pragma unroll
                for (int nt = 0; nt < 4; ++nt)
                    mma16(d[mt][nt], a0, a1, a2, a3, bl[nt][0], bl[nt][1]);
#pragma unroll
                for (int nt = 0; nt < 4; ++nt)
                    mma16(d[mt][nt], a0, a1, a2, a3, bh[nt][0], bh[nt][1]);
#pragma unroll
                for (int nt = 0; nt < 4; ++nt)
                    mma16(d[mt][nt], l0, l1, l2, l3, bh[nt][0], bh[nt][1]);
            }
        }
        __syncthreads();
    }

#pragma unroll
    for (int mt = 0; mt < 4; ++mt) {
        int row = bm + wm*64 + mt*16 + g;
#pragma unroll
        for (int nt = 0; nt < 4; ++nt) {
            int col = bn + wn*32 + nt*8 + tig*2;
            if (col < Nc) {
                *(float2*)&C[(size_t)row*Nc + col]     = make_float2(d[mt][nt][0], d[mt][nt][1]);
                *(float2*)&C[(size_t)(row+8)*Nc + col] = make_float2(d[mt][nt][2], d[mt][nt][3]);
            }
        }
    }
#undef ISSUE_LOADS
}

// ---------------- edge pass (32 points/block; stride S decoupled from O) ----------------
__global__ void edge_kernel(float* __restrict__ G, const int* __restrict__ idx,
                            int O, int S, float* __restrict__ part1, float* __restrict__ part2) {
    int tid = threadIdx.x;
    int o = tid % O;
    int pr = tid / O;
    int R = 256 / O;
    int blk = blockIdx.x;
    int p0 = blk * 32;
    __shared__ int sidx[32*KNN];
    for (int t = tid; t < 32*KNN; t += 256)
        sidx[t] = idx[p0*KNN + t];
    __syncthreads();
    float s1 = 0.0f, s2 = 0.0f;
    for (int pp = pr; pp < 32; pp += R) {
        int p = p0 + pp;
        float u = G[(size_t)p*S + o];
        float zmax = NEG_INF;
#pragma unroll
        for (int k = 0; k < KNN; ++k) {
            int j = sidx[pp*KNN + k];
            float z = G[(size_t)j*S + O + o];
            float v = u + z;
            zmax = fmaxf(zmax, z);
            s1 += v;
            s2 += v*v;
        }
        G[(size_t)p*S + o] = u + zmax;
    }
    __shared__ float red1[256], red2[256];
    red1[tid] = s1; red2[tid] = s2;
    __syncthreads();
    for (int r = R >> 1; r > 0; r >>= 1) {
        if (pr < r) {
            red1[tid] += red1[tid + r*O];
            red2[tid] += red2[tid + r*O];
        }
        __syncthreads();
    }
    if (pr == 0) {
        part1[blk*O + o] = red1[tid];
        part2[blk*O + o] = red2[tid];
    }
}

// ---------------- stats ----------------
__global__ void reduce_stats_kernel(const float* __restrict__ part1,
                                    const float* __restrict__ part2,
                                    const float* __restrict__ g, const float* __restrict__ b,
                                    int O, float invCnt, int stage) {
    int o = blockIdx.x;
    int tid = threadIdx.x;
    float s1 = 0.0f, s2 = 0.0f;
    for (int i = tid; i < 512; i += 256) {
        s1 += part1[(size_t)i*O + o];
        s2 += part2[(size_t)i*O + o];
    }
    __shared__ float r1[256], r2[256];
    r1[tid] = s1; r2[tid] = s2;
    __syncthreads();
    for (int s = 128; s > 0; s >>= 1) {
        if (tid < s) { r1[tid] += r1[tid + s]; r2[tid] += r2[tid + s]; }
        __syncthreads();
    }
    if (tid == 0) {
        float mean = r1[0] * invCnt;
        float var  = r2[0] * invCnt - mean*mean;
        float sc = g[o] * rsqrtf(var + 1e-5f);
        d_scaleA[stage][o] = sc;
        d_shiftA[stage][o] = b[o] - mean * sc;
    }
}

__global__ void colstats_kernel(const float* __restrict__ X, int lda, int O, float invCnt,
                                const float* __restrict__ g, const float* __restrict__ b,
                                int stage) {
    int o = blockIdx.x;
    __shared__ float r1[256], r2[256];
    float s1 = 0.0f, s2 = 0.0f;
    for (int r = threadIdx.x; r < BN_TOT; r += 256) {
        float v = X[(size_t)r*lda + o];
        s1 += v; s2 += v*v;
    }
    r1[threadIdx.x] = s1; r2[threadIdx.x] = s2;
    __syncthreads();
    for (int s = 128; s > 0; s >>= 1) {
        if (threadIdx.x < s) {
            r1[threadIdx.x] += r1[threadIdx.x + s];
            r2[threadIdx.x] += r2[threadIdx.x + s];
        }
        __syncthreads();
    }
    if (threadIdx.x == 0) {
        float mean = r1[0] * invCnt;
        float var  = r2[0] * invCnt - mean*mean;
        float sc = g[o] * rsqrtf(var + 1e-5f);
        d_scaleA[stage][o] = sc;
        d_shiftA[stage][o] = b[o] - mean * sc;
    }
}

// ---------------- pooling ----------------
__global__ void pool_partial_kernel(const float* __restrict__ fused, float* __restrict__ pool) {
    int b = blockIdx.x, ch = blockIdx.y, o = threadIdx.x;
    int n0 = ch * 256;
    float mx = NEG_INF, sm = 0.0f;
    for (int i = 0; i < 256; ++i) {
        float v = fused[((size_t)(b*NN + n0 + i))*256 + o];
        mx = fmaxf(mx, v);
        sm += v;
    }
    pool[((size_t)(b*16 + ch))*512 + o]       = mx;
    pool[((size_t)(b*16 + ch))*512 + 256 + o] = sm;
}

__global__ void pool_combine_kernel(const float* __restrict__ pool, float* __restrict__ h) {
    int b = blockIdx.x, o = threadIdx.x;
    float mx = NEG_INF, sm = 0.0f;
    for (int c = 0; c < 16; ++c) {
        mx = fmaxf(mx, pool[((size_t)(b*16 + c))*512 + o]);
        sm += pool[((size_t)(b*16 + c))*512 + 256 + o];
    }
    h[b*512 + o]       = mx;
    h[b*512 + 256 + o] = sm * (1.0f / (float)NN);
}

// ---------------- classifier head ----------------
__global__ void head1_kernel(const float* __restrict__ w, const float* __restrict__ h,
                             float* __restrict__ y1) {
    int b = blockIdx.x, o = threadIdx.x;
    float acc = 0.0f;
    for (int c = 0; c < 512; ++c)
        acc = fmaf(w[o*512 + c], h[b*512 + c], acc);
    y1[b*256 + o] = acc;
}

__global__ void headbn_kernel(const float* __restrict__ y1, const float* __restrict__ g,
                              const float* __restrict__ b, float* __restrict__ h2) {
    int o = threadIdx.x;
    float v0 = y1[0*256 + o], v1 = y1[1*256 + o], v2 = y1[2*256 + o], v3 = y1[3*256 + o];
    float m = 0.25f * (v0 + v1 + v2 + v3);
    float q0 = v0 - m, q1 = v1 - m, q2 = v2 - m, q3 = v3 - m;
    float var = 0.25f * (q0*q0 + q1*q1 + q2*q2 + q3*q3);
    float sc = g[o] * rsqrtf(var + 1e-5f);
    float bo = b[o];
    h2[0*256 + o] = fmaxf(q0*sc + bo, 0.0f);
    h2[1*256 + o] = fmaxf(q1*sc + bo, 0.0f);
    h2[2*256 + o] = fmaxf(q2*sc + bo, 0.0f);
    h2[3*256 + o] = fmaxf(q3*sc + bo, 0.0f);
}

__global__ void head2_kernel(const float* __restrict__ w, const float* __restrict__ h2,
                             float* __restrict__ out) {
    int t = threadIdx.x;
    if (t >= 160) return;
    int b = t / 40, q = t % 40;
    float acc = 0.0f;
    for (int c = 0; c < 256; ++c)
        acc = fmaf(w[q*256 + c], h2[b*256 + c], acc);
    out[b*40 + q] = acc;
}

// ---------------- host driver ----------------
static float* getF(const void* sym) { void* p = nullptr; cudaGetSymbolAddress(&p, sym); return (float*)p; }
static uint32_t* getU(const void* sym) { void* p = nullptr; cudaGetSymbolAddress(&p, sym); return (uint32_t*)p; }

extern "C" void kernel_launch(void* const* d_in, const int* in_sizes, int n_in,
                              void* d_out, int out_size) {
    const float* x      = (const float*)d_in[0];
    const float* w1     = (const float*)d_in[2];
    const float* g1     = (const float*)d_in[3];
    const float* b1     = (const float*)d_in[4];
    const float* w2     = (const float*)d_in[5];
    const float* g2     = (const float*)d_in[6];
    const float* b2     = (const float*)d_in[7];
    const float* w3     = (const float*)d_in[8];
    const float* g3     = (const float*)d_in[9];
    const float* b3     = (const float*)d_in[10];
    const float* w4     = (const float*)d_in[11];
    const float* g4     = (const float*)d_in[12];
    const float* b4     = (const float*)d_in[13];
    const float* dec_w  = (const float*)d_in[14];
    const float* dec_g  = (const float*)d_in[15];
    const float* dec_b  = (const float*)d_in[16];
    const float* fus_w  = (const float*)d_in[17];
    const float* cls_w1 = (const float*)d_in[18];
    const float* cls_g  = (const float*)d_in[19];
    const float* cls_b  = (const float*)d_in[20];
    const float* cls_w2 = (const float*)d_in[21];
    float* out = (float*)d_out;

    float* CD   = getF(d_candD);
    float* G1   = getF(d_G1);
    float* G2D  = getF(d_G2D);
    float* G3   = getF(d_G3);
    float* G4   = getF(d_G4);
    float* FUS  = getF(d_fused);
    float* P1   = getF(d_part1);
    float* P2   = getF(d_part2);
    float* POOL = getF(d_pool);
    float* H    = getF(d_h);
    float* Y1   = getF(d_y1);
    float* H2   = getF(d_h2);
    uint32_t* AH = getU(d_Ah);
    uint32_t* AL = getU(d_Al);
    uint32_t* WH = getU(d_WhAll);
    uint32_t* WL = getU(d_WlAll);
    void* ip = nullptr; cudaGetSymbolAddress(&ip, d_idx);
    int* IDX = (int*)ip;
    void* cp = nullptr; cudaGetSymbolAddress(&cp, d_candI);
    int* CI = (int*)cp;

    static cudaStream_t s1 = nullptr, s2 = nullptr;
    static cudaEvent_t evRoot, evC1, evW, evG2, evDec;
    static int init_done = 0;
    if (!init_done) {
        cudaFuncSetAttribute(bf_gemm, cudaFuncAttributeMaxDynamicSharedMemorySize, GEMM_SMEM);
        cudaStreamCreateWithFlags(&s1, cudaStreamNonBlocking);
        cudaStreamCreateWithFlags(&s2, cudaStreamNonBlocking);
        cudaEventCreateWithFlags(&evRoot, cudaEventDisableTiming);
        cudaEventCreateWithFlags(&evC1,   cudaEventDisableTiming);
        cudaEventCreateWithFlags(&evW,    cudaEventDisableTiming);
        cudaEventCreateWithFlags(&evG2,   cudaEventDisableTiming);
        cudaEventCreateWithFlags(&evDec,  cudaEventDisableTiming);
        init_done = 1;
    }

    const float invE = 1.0f/(float)(BN_TOT*KNN);

    // fork side streams off capture origin
    cudaEventRecord(evRoot, 0);
    cudaStreamWaitEvent(s1, evRoot, 0);
    cudaStreamWaitEvent(s2, evRoot, 0);

    // main: knn;  s1: conv1;  s2: all weight packs
    knn_part_kernel<<<dim3(BB, NN/256, KS), 256, 0, 0>>>(x, CD, CI);
    knn_merge_kernel<<<(BN_TOT + 255)/256, 256, 0, 0>>>(CD, CI, IDX);
    conv1_kernel<<<BN_TOT*128/4/256, 256, 0, s1>>>(x, w1, G1);
    cudaEventRecord(evC1, s1);
    convW_all_kernel<<<dim3(256, 5), 256, 0, s2>>>(w2, w3, w4, dec_w, fus_w, WH, WL);
    cudaEventRecord(evW, s2);

    // conv1 edge + stats (needs conv1 + knn)
    cudaStreamWaitEvent(0, evC1, 0);
    edge_kernel<<<512, 256, 0, 0>>>(G1, IDX, 64, 128, P1, P2);
    reduce_stats_kernel<<<64, 256, 0, 0>>>(P1, P2, g1, b1, 64, invE, 0);
    convA_kernel<<<(BN_TOT*32 + 255)/256, 256, 0, 0>>>(G1, 128, 64, 32, 0, AH, AL);

    // combined conv2 + dec GEMM (grid.y: 0,1 = conv2 U/Z; 2 = dec)
    cudaStreamWaitEvent(0, evW, 0);
    bf_gemm<<<dim3(BN_TOT/128, 3), 256, GEMM_SMEM, 0>>>(AH, AL, 32, WH + WOFF_C2D, WL + WOFF_C2D, G2D, 384, 2);

    // dec BN stats on s1, concurrent with conv2 edge chain
    cudaEventRecord(evG2, 0);
    cudaStreamWaitEvent(s1, evG2, 0);
    colstats_kernel<<<48, 256, 0, s1>>>(G2D + 256, 384, 48, 1.0f/(float)BN_TOT, dec_g, dec_b, 4);
    cudaEventRecord(evDec, s1);

    edge_kernel<<<512, 256, 0, 0>>>(G2D, IDX, 128, 384, P1, P2);
    reduce_stats_kernel<<<128, 256, 0, 0>>>(P1, P2, g2, b2, 128, invE, 1);

    // conv3
    convA_kernel<<<(BN_TOT*64 + 255)/256, 256, 0, 0>>>(G2D, 384, 128, 64, 1, AH, AL);
    bf_gemm<<<dim3(BN_TOT/128, 4), 256, GEMM_SMEM, 0>>>(AH, AL, 64, WH + WOFF_C3, WL + WOFF_C3, G3, 512, 4);
    edge_kernel<<<512, 256, 0, 0>>>(G3, IDX, 256, 512, P1, P2);
    reduce_stats_kernel<<<256, 256, 0, 0>>>(P1, P2, g3, b3, 256, invE, 2);

    // conv4
    convA_kernel<<<(BN_TOT*128 + 255)/256, 256, 0, 0>>>(G3, 512, 256, 128, 2, AH, AL);
    bf_gemm<<<dim3(BN_TOT/128, 4), 256, GEMM_SMEM, 0>>>(AH, AL, 128, WH + WOFF_C4, WL + WOFF_C4, G4, 512, 8);
    edge_kernel<<<512, 256, 0, 0>>>(G4, IDX, 256, 512, P1, P2);
    reduce_stats_kernel<<<256, 256, 0, 0>>>(P1, P2, g4, b4, 256, invE, 3);

    // fusion (needs dec stats too)
    cudaStreamWaitEvent(0, evDec, 0);
    convCat_kernel<<<(BN_TOT*160 + 255)/256, 256, 0, 0>>>(G4, G2D, AH, AL);
    bf_gemm<<<dim3(BN_TOT/128, 2), 256, GEMM_SMEM, 0>>>(AH, AL, 160, WH + WOFF_FUS, WL + WOFF_FUS, FUS, 256, 10);

    // pool + head
    pool_partial_kernel<<<dim3(4, 16), 256, 0, 0>>>(FUS, POOL);
    pool_combine_kernel<<<4, 256, 0, 0>>>(POOL, H);
    head1_kernel<<<4, 256, 0, 0>>>(cls_w1, H, Y1);
    headbn_kernel<<<1, 256, 0, 0>>>(Y1, cls_g, cls_b, H2);
    head2_kernel<<<1, 160, 0, 0>>>(cls_w2, H2, out);
}

// round 17
// speedup vs baseline: 1.0167x; 1.0167x over previous
#include <cuda_runtime.h>
#include <cstdint>

#define BB 4
#define NN 4096
#define KNN 9
#define KS 4
#define CHUNK (NN/KS)
#define BN_TOT (BB*NN)
#define NEG_INF (-3.402823466e38f)

// ---------------- device scratch ----------------
__device__ int   d_idx[BN_TOT*KNN];
__device__ float d_candD[BN_TOT*KS*KNN];
__device__ int   d_candI[BN_TOT*KS*KNN];
__device__ float d_G1[BN_TOT*128];
__device__ float d_G2D[BN_TOT*384];     // conv2 [U|Z] cols 0..255, dec cols 256..303 (pad to 384)
__device__ float d_G3[BN_TOT*512];
__device__ float d_G4[BN_TOT*512];
__device__ float d_fused[BN_TOT*256];
__device__ float d_part1[1024*256];
__device__ float d_part2[1024*256];
__device__ __align__(16) float d_scaleA[5][256];
__device__ __align__(16) float d_shiftA[5][256];
__device__ __align__(16) uint32_t d_Ah[BN_TOT*160];
__device__ __align__(16) uint32_t d_Al[BN_TOT*160];
__device__ __align__(16) uint32_t d_WhAll[151552];
__device__ __align__(16) uint32_t d_WlAll[151552];
__device__ float d_pool[4*16*512];
__device__ float d_h[4*512];
__device__ float d_y1[4*256];
__device__ float d_h2[4*256];

// W segment offsets (u32): combined conv2+dec, conv3, conv4, fus
#define WOFF_C2D  0              // 384 rows x 32
#define WOFF_DEC  8192           //   dec sub-block at row 256
#define WOFF_C3   12288          // 512 x 64
#define WOFF_C4   45056          // 512 x 128
#define WOFF_FUS  110592         // 256 x 160

// ---------------- helpers ----------------
__device__ __forceinline__ float sq3(float a, float b, float c) {
    return a*a + b*b + c*c;
}
__device__ __forceinline__ uint32_t pack_bf16(float a0, float a1) {
    uint32_t r; asm("cvt.rn.bf16x2.f32 %0, %1, %2;" : "=r"(r) : "f"(a1), "f"(a0));
    return r;
}
__device__ __forceinline__ void split_bf16(float v0, float v1, uint32_t& h, uint32_t& l) {
    h = pack_bf16(v0, v1);
    l = pack_bf16(v0 - __uint_as_float(h << 16),
                  v1 - __uint_as_float(h & 0xffff0000u));
}
__device__ __forceinline__ void mma16(float* d, uint32_t a0, uint32_t a1, uint32_t a2, uint32_t a3,
                                      uint32_t b0, uint32_t b1) {
    asm volatile(
        "mma.sync.aligned.m16n8k16.row.col.f32.bf16.bf16.f32 "
        "{%0,%1,%2,%3},{%4,%5,%6,%7},{%8,%9},{%0,%1,%2,%3};"
        : "+f"(d[0]), "+f"(d[1]), "+f"(d[2]), "+f"(d[3])
        : "r"(a0), "r"(a1), "r"(a2), "r"(a3), "r"(b0), "r"(b1));
}
__device__ __forceinline__ uint32_t smem_u32(const void* p) {
    uint32_t a;
    asm("{ .reg .u64 t; cvta.to.shared.u64 t, %1; cvt.u32.u64 %0, t; }" : "=r"(a) : "l"(p));
    return a;
}
#define LDSM4(r0,r1,r2,r3,addr) \
    asm volatile("ldmatrix.sync.aligned.m8n8.x4.shared.b16 {%0,%1,%2,%3}, [%4];" \
        : "=r"(r0),"=r"(r1),"=r"(r2),"=r"(r3) : "r"(addr))
#define CP_ASYNC16(s, g) \
    asm volatile("cp.async.cg.shared.global [%0], [%1], 16;" :: "r"(s), "l"(g))
#define CP_COMMIT()  asm volatile("cp.async.commit_group;" ::: "memory")
#define CP_WAIT1()   asm volatile("cp.async.wait_group 1;" ::: "memory")

// ---------------- knn (reads x directly; x layout (b,3,N)) ----------------
__global__ void knn_part_kernel(const float* __restrict__ x,
                                float* __restrict__ candD, int* __restrict__ candI) {
    __shared__ float sx[CHUNK], sy[CHUNK], sz[CHUNK], s2[CHUNK];
    int b  = blockIdx.x;
    int n  = blockIdx.y * blockDim.x + threadIdx.x;
    int cs = blockIdx.z;
    int m0 = cs * CHUNK;
    const float* xb0 = x + (size_t)(b*3+0)*NN;
    const float* xb1 = x + (size_t)(b*3+1)*NN;
    const float* xb2 = x + (size_t)(b*3+2)*NN;
    for (int t = threadIdx.x; t < CHUNK; t += blockDim.x) {
        int m = m0 + t;
        float a = xb0[m], bb = xb1[m], c = xb2[m];
        sx[t] = a; sy[t] = bb; sz[t] = c;
        s2[t] = sq3(a, bb, c);
    }
    __syncthreads();
    float px = xb0[n], py = xb1[n], pz = xb2[n];
    float p2 = sq3(px, py, pz);
    float bd[KNN]; int bi[KNN];
#pragma unroll
    for (int j = 0; j < KNN; ++j) { bd[j] = 1e30f; bi[j] = 0; }
#pragma unroll 4
    for (int mm = 0; mm < CHUNK; ++mm) {
        float dot = px*sx[mm] + py*sy[mm] + pz*sz[mm];
        float d = p2 + s2[mm] - 2.0f*dot;
        int m = m0 + mm;
        if (m == n) d = 1e30f;
        if (d < bd[KNN-1]) {
            float vd = d; int vi = m;
#pragma unroll
            for (int j = 0; j < KNN; ++j) {
                if (vd < bd[j]) {
                    float td = bd[j]; bd[j] = vd; vd = td;
                    int   ti = bi[j]; bi[j] = vi; vi = ti;
                }
            }
        }
    }
    size_t base = ((size_t)(b*NN + n)*KS + cs)*KNN;
#pragma unroll
    for (int j = 0; j < KNN; ++j) {
        candD[base + j] = bd[j];
        candI[base + j] = bi[j];
    }
}

__global__ void knn_merge_kernel(const float* __restrict__ candD, const int* __restrict__ candI,
                                 int* __restrict__ idxOut) {
    int t = blockIdx.x * blockDim.x + threadIdx.x;
    if (t >= BN_TOT) return;
    int b = t / NN;
    float bd[KNN]; int bi[KNN];
#pragma unroll
    for (int j = 0; j < KNN; ++j) { bd[j] = 1e30f; bi[j] = 0; }
    size_t base = (size_t)t*KS*KNN;
    for (int c = 0; c < KS*KNN; ++c) {
        float d = candD[base + c];
        int   m = candI[base + c];
        if (d < bd[KNN-1]) {
            float vd = d; int vi = m;
#pragma unroll
            for (int j = 0; j < KNN; ++j) {
                if (vd < bd[j]) {
                    float td = bd[j]; bd[j] = vd; vd = td;
                    int   ti = bi[j]; bi[j] = vi; vi = ti;
                }
            }
        }
    }
#pragma unroll
    for (int j = 0; j < KNN; ++j)
        idxOut[t*KNN + j] = b*NN + bi[j];
}

// ---------------- conv1 (Kc=3, reads x directly) ----------------
__global__ void conv1_kernel(const float* __restrict__ x, const float* __restrict__ w1,
                             float* __restrict__ G) {
    __shared__ float cw0[128], cw1[128], cw2[128];
    int tid = threadIdx.x;
    if (tid < 128) {
        if (tid < 64) {
            cw0[tid] = w1[tid*6+0] - w1[tid*6+3];
            cw1[tid] = w1[tid*6+1] - w1[tid*6+4];
            cw2[tid] = w1[tid*6+2] - w1[tid*6+5];
        } else {
            int q = tid - 64;
            cw0[tid] = w1[q*6+3]; cw1[tid] = w1[q*6+4]; cw2[tid] = w1[q*6+5];
        }
    }
    __syncthreads();
    int t4 = blockIdx.x * blockDim.x + tid;
    if (t4 >= BN_TOT*128/4) return;
    int t = t4 * 4;
    int p = t >> 7, o = t & 127;
    int b = p >> 12, n = p & (NN - 1);
    float x0 = x[(size_t)(b*3+0)*NN + n];
    float x1 = x[(size_t)(b*3+1)*NN + n];
    float x2 = x[(size_t)(b*3+2)*NN + n];
    float4 r;
    r.x = cw0[o+0]*x0 + cw1[o+0]*x1 + cw2[o+0]*x2;
    r.y = cw0[o+1]*x0 + cw1[o+1]*x1 + cw2[o+1]*x2;
    r.z = cw0[o+2]*x0 + cw1[o+2]*x1 + cw2[o+2]*x2;
    r.w = cw0[o+3]*x0 + cw1[o+3]*x1 + cw2[o+3]*x2;
    *(float4*)&G[t] = r;
}

// ---------------- all weight packs in ONE launch ----------------
__device__ __forceinline__ void pack_w_seg(const float* __restrict__ W, int wmode, int O, int Nc,
                                           int Kc, int K2, int Npad,
                                           uint32_t* __restrict__ Wh, uint32_t* __restrict__ Wl) {
    int total = Npad * K2;
    for (int t = blockIdx.x * blockDim.x + threadIdx.x; t < total; t += gridDim.x * blockDim.x) {
        int n = t / K2, k2 = t % K2;
        int k = 2*k2;
        float v0 = 0.f, v1 = 0.f;
        if (k < Kc) {
            if (wmode == 1) {
                if (n < O) {
                    v0 = W[(size_t)n*2*Kc + k]     - W[(size_t)n*2*Kc + Kc + k];
                    v1 = W[(size_t)n*2*Kc + k + 1] - W[(size_t)n*2*Kc + Kc + k + 1];
                } else if (n < 2*O) {
                    v0 = W[(size_t)(n-O)*2*Kc + Kc + k];
                    v1 = W[(size_t)(n-O)*2*Kc + Kc + k + 1];
                }
            } else if (n < Nc) {
                v0 = W[(size_t)n*Kc + k];
                v1 = W[(size_t)n*Kc + k + 1];
            }
        }
        uint32_t h, l; split_bf16(v0, v1, h, l);
        Wh[t] = h; Wl[t] = l;
    }
}

__global__ void convW_all_kernel(const float* __restrict__ w2, const float* __restrict__ w3,
                                 const float* __restrict__ w4, const float* __restrict__ dec_w,
                                 const float* __restrict__ fus_w,
                                 uint32_t* __restrict__ Wh, uint32_t* __restrict__ Wl) {
    switch (blockIdx.y) {
        case 0: pack_w_seg(w2,    1, 128, 256,  64,  32, 256, Wh + WOFF_C2D, Wl + WOFF_C2D); break;
        case 1: pack_w_seg(w3,    1, 256, 512, 128,  64, 512, Wh + WOFF_C3,  Wl + WOFF_C3);  break;
        case 2: pack_w_seg(w4,    1, 256, 512, 256, 128, 512, Wh + WOFF_C4,  Wl + WOFF_C4);  break;
        case 3: pack_w_seg(dec_w, 0,   0,  48,  64,  32, 128, Wh + WOFF_DEC, Wl + WOFF_DEC); break;
        case 4: pack_w_seg(fus_w, 0,   0, 256, 304, 160, 256, Wh + WOFF_FUS, Wl + WOFF_FUS); break;
    }
}

// ---------------- preconvert A (lda-strided source) ----------------
__global__ void convA_kernel(const float* __restrict__ src, int lda, int Kc, int K2,
                             int stage, uint32_t* __restrict__ Ah, uint32_t* __restrict__ Al) {
    int t = blockIdx.x * blockDim.x + threadIdx.x;
    if (t >= BN_TOT*K2) return;
    int p = t / K2, k2 = t % K2;
    int k = 2*k2;
    float v0 = 0.f, v1 = 0.f;
    if (k < Kc) {
        v0 = src[(size_t)p*lda + k];
        v1 = src[(size_t)p*lda + k + 1];
        if (stage >= 0) {
            v0 = fmaxf(fmaf(v0, d_scaleA[stage][k],   d_shiftA[stage][k]),   0.0f);
            v1 = fmaxf(fmaf(v1, d_scaleA[stage][k+1], d_shiftA[stage][k+1]), 0.0f);
        }
    }
    uint32_t h, l; split_bf16(v0, v1, h, l);
    Ah[t] = h; Al[t] = l;
}

// ---------------- cat -> packed (Gdec inside G2D at col 256, stride 384) ----------------
__global__ void convCat_kernel(const float* __restrict__ G4, const float* __restrict__ G2D,
                               uint32_t* __restrict__ Ah, uint32_t* __restrict__ Al) {
    int t = blockIdx.x * blockDim.x + threadIdx.x;
    if (t >= BN_TOT*160) return;
    int p = t / 160, k2 = t % 160;
    int k = 2*k2;
    float v0 = 0.f, v1 = 0.f;
    if (k < 256) {
        v0 = fmaxf(fmaf(G4[(size_t)p*512 + k],   d_scaleA[3][k],   d_shiftA[3][k]),   0.0f);
        v1 = fmaxf(fmaf(G4[(size_t)p*512 + k+1], d_scaleA[3][k+1], d_shiftA[3][k+1]), 0.0f);
    } else if (k < 304) {
        int q = k - 256;
        v0 = fmaxf(fmaf(G2D[(size_t)p*384 + 256 + q],   d_scaleA[4][q],   d_shiftA[4][q]),   0.0f);
        if (q + 1 < 48)
            v1 = fmaxf(fmaf(G2D[(size_t)p*384 + 256 + q+1], d_scaleA[4][q+1], d_shiftA[4][q+1]), 0.0f);
    }
    uint32_t h, l; split_bf16(v0, v1, h, l);
    Ah[t] = h; Al[t] = l;
}

// ---------------- bf16x3 GEMM ----------------
#define GS_ROW 20
#define GS_ARR (128*GS_ROW)
#define GS_BUF (4*GS_ARR)
#define GEMM_SMEM (2*GS_BUF*4)

__global__ __launch_bounds__(256, 2)
void bf_gemm(const uint32_t* __restrict__ Ah, const uint32_t* __restrict__ Al, int sK2,
             const uint32_t* __restrict__ Wh, const uint32_t* __restrict__ Wl,
             float* __restrict__ C, int Nc, int nIter) {
    extern __shared__ uint32_t sm[];
    uint32_t sbase = smem_u32(sm);

    int tid = threadIdx.x;
    int lane = tid & 31, wid = tid >> 5;
    int wm = wid >> 2, wn = wid & 3;
    int g = lane >> 2, tig = lane & 3;
    int bm = blockIdx.x * 128;
    int bn = blockIdx.y * 128;

    float d[4][4][4];
#pragma unroll
    for (int i = 0; i < 4; ++i)
#pragma unroll
        for (int j = 0; j < 4; ++j)
#pragma unroll
            for (int q = 0; q < 4; ++q) d[i][j][q] = 0.0f;

#define ISSUE_LOADS(IT, BUFO)                                                   \
    {                                                                           \
        int k2o = (IT)*16;                                                      \
        _Pragma("unroll")                                                       \
        for (int i = 0; i < 8; ++i) {                                           \
            int c   = tid + i*256;                                              \
            int arr = c >> 9;                                                   \
            int rr  = (c & 511) >> 2;                                           \
            int col = c & 3;                                                    \
            const uint32_t* gp;                                                 \
            if (arr == 0)      gp = Ah + (size_t)(bm + rr)*sK2 + k2o + col*4;   \
            else if (arr == 1) gp = Al + (size_t)(bm + rr)*sK2 + k2o + col*4;   \
            else if (arr == 2) gp = Wh + (size_t)(bn + rr)*sK2 + k2o + col*4;   \
            else               gp = Wl + (size_t)(bn + rr)*sK2 + k2o + col*4;   \
            uint32_t sa = sbase + ((BUFO) + arr*GS_ARR + rr*GS_ROW + col*4)*4;  \
            CP_ASYNC16(sa, gp);                                                 \
        }                                                                       \
    }

    ISSUE_LOADS(0, 0)
    CP_COMMIT();

    int aRow = ((lane >> 3) & 1)*8 + (lane & 7);
    int aChk = lane >> 4;
    int bRow = ((lane >> 4) & 1)*8 + (lane & 7);
    int bChk = (lane >> 3) & 1;

    for (int it = 0; it < nIter; ++it) {
        int bufo = (it & 1) * GS_BUF;
        int nxto = ((it + 1) & 1) * GS_BUF;
        if (it + 1 < nIter) ISSUE_LOADS(it + 1, nxto)
        CP_COMMIT();
        CP_WAIT1();
        __syncthreads();

        uint32_t ahB = sbase + (bufo + 0*GS_ARR)*4;
        uint32_t alB = sbase + (bufo + 1*GS_ARR)*4;
        uint32_t bhB = sbase + (bufo + 2*GS_ARR)*4;
        uint32_t blB = sbase + (bufo + 3*GS_ARR)*4;

#pragma unroll
        for (int ks = 0; ks < 2; ++ks) {
            uint32_t bh[4][2], bl[4][2];
#pragma unroll
            for (int p = 0; p < 2; ++p) {
                uint32_t off = ((wn*32 + p*16 + bRow)*GS_ROW + (ks*2 + bChk)*4)*4;
                LDSM4(bh[2*p][0], bh[2*p][1], bh[2*p+1][0], bh[2*p+1][1], bhB + off);
                LDSM4(bl[2*p][0], bl[2*p][1], bl[2*p+1][0], bl[2*p+1][1], blB + off);
            }
#pragma unroll
            for (int mt = 0; mt < 4; ++mt) {
                uint32_t a0, a1, a2, a3, l0, l1, l2, l3;
                uint32_t off = ((wm*64 + mt*16 + aRow)*GS_ROW + (ks*2 + aChk)*4)*4;
                LDSM4(a0, a1, a2, a3, ahB + off);
                LDSM4(l0, l1, l2, l3, alB + off);
#pragma unroll
                for (int nt = 0; nt < 4; ++nt) {
                    mma16(d[mt][nt], a0, a1, a2, a3, bl[nt][0], bl[nt][1]);
                    mma16(d[mt][nt], a0, a1, a2, a3, bh[nt][0], bh[nt][1]);
                    mma16(d[mt][nt], l0, l1, l2, l3, bh[nt][0], bh[nt][1]);
                }
            }
        }
        __syncthreads();
    }

#pragma unroll
    for (int mt = 0; mt < 4; ++mt) {
        int row = bm + wm*64 + mt*16 + g;
#pragma unroll
        for (int nt = 0; nt < 4; ++nt) {
            int col = bn + wn*32 + nt*8 + tig*2;
            if (col < Nc) {
                *(float2*)&C[(size_t)row*Nc + col]     = make_float2(d[mt][nt][0], d[mt][nt][1]);
                *(float2*)&C[(size_t)(row+8)*Nc + col] = make_float2(d[mt][nt][2], d[mt][nt][3]);
            }
        }
    }
#undef ISSUE_LOADS
}

// ---------------- edge pass (16 points/block; stride S decoupled from O) ----------------
__global__ void edge_kernel(float* __restrict__ G, const int* __restrict__ idx,
                            int O, int S, float* __restrict__ part1, float* __restrict__ part2) {
    int tid = threadIdx.x;
    int o = tid % O;
    int pr = tid / O;
    int R = 256 / O;
    int blk = blockIdx.x;
    int p0 = blk * 16;
    __shared__ int sidx[16*KNN];
    for (int t = tid; t < 16*KNN; t += 256)
        sidx[t] = idx[p0*KNN + t];
    __syncthreads();
    float s1 = 0.0f, s2 = 0.0f;
    for (int pp = pr; pp < 16; pp += R) {
        int p = p0 + pp;
        float u = G[(size_t)p*S + o];
        float zmax = NEG_INF;
#pragma unroll
        for (int k = 0; k < KNN; ++k) {
            int j = sidx[pp*KNN + k];
            float z = G[(size_t)j*S + O + o];
            float v = u + z;
            zmax = fmaxf(zmax, z);
            s1 += v;
            s2 += v*v;
        }
        G[(size_t)p*S + o] = u + zmax;
    }
    __shared__ float red1[256], red2[256];
    red1[tid] = s1; red2[tid] = s2;
    __syncthreads();
    for (int r = R >> 1; r > 0; r >>= 1) {
        if (pr < r) {
            red1[tid] += red1[tid + r*O];
            red2[tid] += red2[tid + r*O];
        }
        __syncthreads();
    }
    if (pr == 0) {
        part1[blk*O + o] = red1[tid];
        part2[blk*O + o] = red2[tid];
    }
}

// ---------------- stats ----------------
__global__ void reduce_stats_kernel(const float* __restrict__ part1,
                                    const float* __restrict__ part2,
                                    const float* __restrict__ g, const float* __restrict__ b,
                                    int O, float invCnt, int stage) {
    int o = blockIdx.x;
    int tid = threadIdx.x;
    float s1 = 0.0f, s2 = 0.0f;
    for (int i = tid; i < 1024; i += 256) {
        s1 += part1[(size_t)i*O + o];
        s2 += part2[(size_t)i*O + o];
    }
    __shared__ float r1[256], r2[256];
    r1[tid] = s1; r2[tid] = s2;
    __syncthreads();
    for (int s = 128; s > 0; s >>= 1) {
        if (tid < s) { r1[tid] += r1[tid + s]; r2[tid] += r2[tid + s]; }
        __syncthreads();
    }
    if (tid == 0) {
        float mean = r1[0] * invCnt;
        float var  = r2[0] * invCnt - mean*mean;
        float sc = g[o] * rsqrtf(var + 1e-5f);
        d_scaleA[stage][o] = sc;
        d_shiftA[stage][o] = b[o] - mean * sc;
    }
}

__global__ void colstats_kernel(const float* __restrict__ X, int lda, int O, float invCnt,
                                const float* __restrict__ g, const float* __restrict__ b,
                                int stage) {
    int o = blockIdx.x;
    __shared__ float r1[256], r2[256];
    float s1 = 0.0f, s2 = 0.0f;
    for (int r = threadIdx.x; r < BN_TOT; r += 256) {
        float v = X[(size_t)r*lda + o];
        s1 += v; s2 += v*v;
    }
    r1[threadIdx.x] = s1; r2[threadIdx.x] = s2;
    __syncthreads();
    for (int s = 128; s > 0; s >>= 1) {
        if (threadIdx.x < s) {
            r1[threadIdx.x] += r1[threadIdx.x + s];
            r2[threadIdx.x] += r2[threadIdx.x + s];
        }
        __syncthreads();
    }
    if (threadIdx.x == 0) {
        float mean = r1[0] * invCnt;
        float var  = r2[0] * invCnt - mean*mean;
        float sc = g[o] * rsqrtf(var + 1e-5f);
        d_scaleA[stage][o] = sc;
        d_shiftA[stage][o] = b[o] - mean * sc;
    }
}

// ---------------- pooling ----------------
__global__ void pool_partial_kernel(const float* __restrict__ fused, float* __restrict__ pool) {
    int b = blockIdx.x, ch = blockIdx.y, o = threadIdx.x;
    int n0 = ch * 256;
    float mx = NEG_INF, sm = 0.0f;
    for (int i = 0; i < 256; ++i) {
        float v = fused[((size_t)(b*NN + n0 + i))*256 + o];
        mx = fmaxf(mx, v);
        sm += v;
    }
    pool[((size_t)(b*16 + ch))*512 + o]       = mx;
    pool[((size_t)(b*16 + ch))*512 + 256 + o] = sm;
}

__global__ void pool_combine_kernel(const float* __restrict__ pool, float* __restrict__ h) {
    int b = blockIdx.x, o = threadIdx.x;
    float mx = NEG_INF, sm = 0.0f;
    for (int c = 0; c < 16; ++c) {
        mx = fmaxf(mx, pool[((size_t)(b*16 + c))*512 + o]);
        sm += pool[((size_t)(b*16 + c))*512 + 256 + o];
    }
    h[b*512 + o]       = mx;
    h[b*512 + 256 + o] = sm * (1.0f / (float)NN);
}

// ---------------- classifier head ----------------
__global__ void head1_kernel(const float* __restrict__ w, const float* __restrict__ h,
                             float* __restrict__ y1) {
    int b = blockIdx.x, o = threadIdx.x;
    float acc = 0.0f;
    for (int c = 0; c < 512; ++c)
        acc = fmaf(w[o*512 + c], h[b*512 + c], acc);
    y1[b*256 + o] = acc;
}

__global__ void headbn_kernel(const float* __restrict__ y1, const float* __restrict__ g,
                              const float* __restrict__ b, float* __restrict__ h2) {
    int o = threadIdx.x;
    float v0 = y1[0*256 + o], v1 = y1[1*256 + o], v2 = y1[2*256 + o], v3 = y1[3*256 + o];
    float m = 0.25f * (v0 + v1 + v2 + v3);
    float q0 = v0 - m, q1 = v1 - m, q2 = v2 - m, q3 = v3 - m;
    float var = 0.25f * (q0*q0 + q1*q1 + q2*q2 + q3*q3);
    float sc = g[o] * rsqrtf(var + 1e-5f);
    float bo = b[o];
    h2[0*256 + o] = fmaxf(q0*sc + bo, 0.0f);
    h2[1*256 + o] = fmaxf(q1*sc + bo, 0.0f);
    h2[2*256 + o] = fmaxf(q2*sc + bo, 0.0f);
    h2[3*256 + o] = fmaxf(q3*sc + bo, 0.0f);
}

__global__ void head2_kernel(const float* __restrict__ w, const float* __restrict__ h2,
                             float* __restrict__ out) {
    int t = threadIdx.x;
    if (t >= 160) return;
    int b = t / 40, q = t % 40;
    float acc = 0.0f;
    for (int c = 0; c < 256; ++c)
        acc = fmaf(w[q*256 + c], h2[b*256 + c], acc);
    out[b*40 + q] = acc;
}

// ---------------- host driver ----------------
static float* getF(const void* sym) { void* p = nullptr; cudaGetSymbolAddress(&p, sym); return (float*)p; }
static uint32_t* getU(const void* sym) { void* p = nullptr; cudaGetSymbolAddress(&p, sym); return (uint32_t*)p; }

extern "C" void kernel_launch(void* const* d_in, const int* in_sizes, int n_in,
                              void* d_out, int out_size) {
    const float* x      = (const float*)d_in[0];
    const float* w1     = (const float*)d_in[2];
    const float* g1     = (const float*)d_in[3];
    const float* b1     = (const float*)d_in[4];
    const float* w2     = (const float*)d_in[5];
    const float* g2     = (const float*)d_in[6];
    const float* b2     = (const float*)d_in[7];
    const float* w3     = (const float*)d_in[8];
    const float* g3     = (const float*)d_in[9];
    const float* b3     = (const float*)d_in[10];
    const float* w4     = (const float*)d_in[11];
    const float* g4     = (const float*)d_in[12];
    const float* b4     = (const float*)d_in[13];
    const float* dec_w  = (const float*)d_in[14];
    const float* dec_g  = (const float*)d_in[15];
    const float* dec_b  = (const float*)d_in[16];
    const float* fus_w  = (const float*)d_in[17];
    const float* cls_w1 = (const float*)d_in[18];
    const float* cls_g  = (const float*)d_in[19];
    const float* cls_b  = (const float*)d_in[20];
    const float* cls_w2 = (const float*)d_in[21];
    float* out = (float*)d_out;

    float* CD   = getF(d_candD);
    float* G1   = getF(d_G1);
    float* G2D  = getF(d_G2D);
    float* G3   = getF(d_G3);
    float* G4   = getF(d_G4);
    float* FUS  = getF(d_fused);
    float* P1   = getF(d_part1);
    float* P2   = getF(d_part2);
    float* POOL = getF(d_pool);
    float* H    = getF(d_h);
    float* Y1   = getF(d_y1);
    float* H2   = getF(d_h2);
    uint32_t* AH = getU(d_Ah);
    uint32_t* AL = getU(d_Al);
    uint32_t* WH = getU(d_WhAll);
    uint32_t* WL = getU(d_WlAll);
    void* ip = nullptr; cudaGetSymbolAddress(&ip, d_idx);
    int* IDX = (int*)ip;
    void* cp = nullptr; cudaGetSymbolAddress(&cp, d_candI);
    int* CI = (int*)cp;

    static cudaStream_t s1 = nullptr, s2 = nullptr;
    static cudaEvent_t evRoot, evC1, evW, evG2, evDec;
    static int init_done = 0;
    if (!init_done) {
        cudaFuncSetAttribute(bf_gemm, cudaFuncAttributeMaxDynamicSharedMemorySize, GEMM_SMEM);
        cudaStreamCreateWithFlags(&s1, cudaStreamNonBlocking);
        cudaStreamCreateWithFlags(&s2, cudaStreamNonBlocking);
        cudaEventCreateWithFlags(&evRoot, cudaEventDisableTiming);
        cudaEventCreateWithFlags(&evC1,   cudaEventDisableTiming);
        cudaEventCreateWithFlags(&evW,    cudaEventDisableTiming);
        cudaEventCreateWithFlags(&evG2,   cudaEventDisableTiming);
        cudaEventCreateWithFlags(&evDec,  cudaEventDisableTiming);
        init_done = 1;
    }

    const float invE = 1.0f/(float)(BN_TOT*KNN);

    // fork side streams off capture origin
    cudaEventRecord(evRoot, 0);
    cudaStreamWaitEvent(s1, evRoot, 0);
    cudaStreamWaitEvent(s2, evRoot, 0);

    // main: knn;  s1: conv1;  s2: all weight packs
    knn_part_kernel<<<dim3(BB, NN/128, KS), 128, 0, 0>>>(x, CD, CI);
    knn_merge_kernel<<<(BN_TOT + 255)/256, 256, 0, 0>>>(CD, CI, IDX);
    conv1_kernel<<<BN_TOT*128/4/256, 256, 0, s1>>>(x, w1, G1);
    cudaEventRecord(evC1, s1);
    convW_all_kernel<<<dim3(256, 5), 256, 0, s2>>>(w2, w3, w4, dec_w, fus_w, WH, WL);
    cudaEventRecord(evW, s2);

    // conv1 edge + stats (needs conv1 + knn)
    cudaStreamWaitEvent(0, evC1, 0);
    edge_kernel<<<1024, 256, 0, 0>>>(G1, IDX, 64, 128, P1, P2);
    reduce_stats_kernel<<<64, 256, 0, 0>>>(P1, P2, g1, b1, 64, invE, 0);
    convA_kernel<<<(BN_TOT*32 + 255)/256, 256, 0, 0>>>(G1, 128, 64, 32, 0, AH, AL);

    // combined conv2 + dec GEMM (grid.y: 0,1 = conv2 U/Z; 2 = dec)
    cudaStreamWaitEvent(0, evW, 0);
    bf_gemm<<<dim3(BN_TOT/128, 3), 256, GEMM_SMEM, 0>>>(AH, AL, 32, WH + WOFF_C2D, WL + WOFF_C2D, G2D, 384, 2);

    // dec BN stats on s1, concurrent with conv2 edge chain
    cudaEventRecord(evG2, 0);
    cudaStreamWaitEvent(s1, evG2, 0);
    colstats_kernel<<<48, 256, 0, s1>>>(G2D + 256, 384, 48, 1.0f/(float)BN_TOT, dec_g, dec_b, 4);
    cudaEventRecord(evDec, s1);

    edge_kernel<<<1024, 256, 0, 0>>>(G2D, IDX, 128, 384, P1, P2);
    reduce_stats_kernel<<<128, 256, 0, 0>>>(P1, P2, g2, b2, 128, invE, 1);

    // conv3
    convA_kernel<<<(BN_TOT*64 + 255)/256, 256, 0, 0>>>(G2D, 384, 128, 64, 1, AH, AL);
    bf_gemm<<<dim3(BN_TOT/128, 4), 256, GEMM_SMEM, 0>>>(AH, AL, 64, WH + WOFF_C3, WL + WOFF_C3, G3, 512, 4);
    edge_kernel<<<1024, 256, 0, 0>>>(G3, IDX, 256, 512, P1, P2);
    reduce_stats_kernel<<<256, 256, 0, 0>>>(P1, P2, g3, b3, 256, invE, 2);

    // conv4
    convA_kernel<<<(BN_TOT*128 + 255)/256, 256, 0, 0>>>(G3, 512, 256, 128, 2, AH, AL);
    bf_gemm<<<dim3(BN_TOT/128, 4), 256, GEMM_SMEM, 0>>>(AH, AL, 128, WH + WOFF_C4, WL + WOFF_C4, G4, 512, 8);
    edge_kernel<<<1024, 256, 0, 0>>>(G4, IDX, 256, 512, P1, P2);
    reduce_stats_kernel<<<256, 256, 0, 0>>>(P1, P2, g4, b4, 256, invE, 3);

    // fusion (needs dec stats too)
    cudaStreamWaitEvent(0, evDec, 0);
    convCat_kernel<<<(BN_TOT*160 + 255)/256, 256, 0, 0>>>(G4, G2D, AH, AL);
    bf_gemm<<<dim3(BN_TOT/128, 2), 256, GEMM_SMEM, 0>>>(AH, AL, 160, WH + WOFF_FUS, WL + WOFF_FUS, FUS, 256, 10);

    // pool + head
    pool_partial_kernel<<<dim3(4, 16), 256, 0, 0>>>(FUS, POOL);
    pool_combine_kernel<<<4, 256, 0, 0>>>(POOL, H);
    head1_kernel<<<4, 256, 0, 0>>>(cls_w1, H, Y1);
    headbn_kernel<<<1, 256, 0, 0>>>(Y1, cls_g, cls_b, H2);
    head2_kernel<<<1, 160, 0, 0>>>(cls_w2, H2, out);
}